// round 9
// baseline (speedup 1.0000x reference)
#include <cuda_runtime.h>

// out[b,i,j,c1,c2,k]: k=0 -> x[b,i,c1,c2], k=1 -> x[b,j,c1,c2]
// B=64, GS=96, C=8. Tile (b,i) = 96 j-rows of 128 interleaved floats.
//
// Persistent grid: 148*8 = 1184 CTAs, grid-stride over 6144 (b,i) tiles.
// __launch_bounds__(256, 8) caps regs at 32 so all 8 CTAs/SM are resident
// (R8 regression root-cause: 39 regs -> 6 CTAs/SM -> 1.33 waves).
// Per tile: 1 xi LDG.128 + 6 xj LDG.128 (MLP=6), then 6 STG.256 .cs stores.

static constexpr int GS = 96;
static constexpr int ROW = 64;          // 8*8 floats per (b,g) block
static constexpr int NTILES = 64 * GS;  // 6144
static constexpr int NBLK = 148 * 8;    // 1184 persistent CTAs

__global__ void __launch_bounds__(256, 8)
combo_kernel(const float* __restrict__ x, float* __restrict__ out)
{
    const int t = threadIdx.x;
    const int lane16 = t & 15;            // element-group within tile
    const int jbase  = t >> 4;            // 0..15

    const int lane_off = lane16 * 4;

    for (int bi = blockIdx.x; bi < NTILES; bi += NBLK) {
        // xi: this thread's 4 elements of x[b,i], loop-invariant over j
        const float4 a =
            *reinterpret_cast<const float4*>(x + bi * ROW + lane_off);

        const float* xb = x + (bi / GS) * GS * ROW + lane_off;  // x[b,0] + off
        float* outb = out + (size_t)bi * GS * 128 + lane16 * 8; // out[b,i,0]+off

        // Preload all 6 xj vectors (independent loads, MLP=6)
        float4 c[6];
#pragma unroll
        for (int it = 0; it < 6; ++it) {
            const int j = jbase + it * 16;
            c[it] = *reinterpret_cast<const float4*>(xb + j * ROW);
        }

        // 6 back-to-back 256-bit streaming stores (evict-first: pure stream)
#pragma unroll
        for (int it = 0; it < 6; ++it) {
            const int j = jbase + it * 16;
            float* p = outb + j * 128;
            asm volatile(
                "st.global.cs.v8.f32 [%0], {%1,%2,%3,%4,%5,%6,%7,%8};" ::
                "l"(p),
                "f"(a.x), "f"(c[it].x), "f"(a.y), "f"(c[it].y),
                "f"(a.z), "f"(c[it].z), "f"(a.w), "f"(c[it].w)
                : "memory");
        }
    }
}

extern "C" void kernel_launch(void* const* d_in, const int* in_sizes, int n_in,
                              void* d_out, int out_size)
{
    const float* x = (const float*)d_in[0];
    float* out = (float*)d_out;

    combo_kernel<<<NBLK, 256>>>(x, out);
}

// round 10
// speedup vs baseline: 1.1622x; 1.1622x over previous
#include <cuda_runtime.h>
#include <cstdint>

// out[b,i,j,c1,c2,k]: k=0 -> x[b,i,c1,c2], k=1 -> x[b,j,c1,c2]
// B=64, GS=96, C=8. One CTA per (b,i): builds the full 96x128-float
// interleaved tile (49152 B, contiguous in gmem) in SMEM, then drains it
// with ONE cp.async.bulk SMEM->GMEM (TMA path) — bypasses the l1tex
// per-thread store-wavefront pipeline that reads 70% busy in R6.

static constexpr int GS  = 96;
static constexpr int ROW = 64;                  // 8*8 floats per (b,g) block
static constexpr int TILE_FLOATS = GS * 128;    // 12288
static constexpr int TILE_BYTES  = TILE_FLOATS * 4;  // 49152

__global__ void __launch_bounds__(256)
combo_kernel(const float* __restrict__ x, float* __restrict__ out)
{
    __shared__ __align__(1024) float s[TILE_FLOATS];

    const int bi = blockIdx.x;            // b*GS + i
    const int t = threadIdx.x;
    const int lane16 = t & 15;
    const int jbase  = t >> 4;

    // xi: this thread's 4 elements of x[b,i]
    const float4 a = *reinterpret_cast<const float4*>(x + bi * ROW + lane16 * 4);
    const float* xb = x + (bi / GS) * GS * ROW + lane16 * 4;

#pragma unroll
    for (int it = 0; it < 6; ++it) {
        const int j = jbase + it * 16;
        const float4 c = *reinterpret_cast<const float4*>(xb + j * ROW);
        float4* sp = reinterpret_cast<float4*>(s + j * 128 + lane16 * 8);
        sp[0] = make_float4(a.x, c.x, a.y, c.y);
        sp[1] = make_float4(a.z, c.z, a.w, c.w);
    }
    __syncthreads();

    if (t == 0) {
        // order generic-proxy SMEM writes before async-proxy (TMA) read
        asm volatile("fence.proxy.async.shared::cta;" ::: "memory");
        uint32_t saddr = (uint32_t)__cvta_generic_to_shared(s);
        float* g = out + (size_t)bi * TILE_FLOATS;
        asm volatile(
            "cp.async.bulk.global.shared::cta.bulk_group [%0], [%1], %2;"
            :: "l"(g), "r"(saddr), "n"(TILE_BYTES) : "memory");
        asm volatile("cp.async.bulk.commit_group;" ::: "memory");
        asm volatile("cp.async.bulk.wait_group 0;" ::: "memory");
    }
}

extern "C" void kernel_launch(void* const* d_in, const int* in_sizes, int n_in,
                              void* d_out, int out_size)
{
    const float* x = (const float*)d_in[0];
    float* out = (float*)d_out;

    combo_kernel<<<64 * GS, 256>>>(x, out);   // 6144 CTAs, one per (b,i)
}